// round 2
// baseline (speedup 1.0000x reference)
#include <cuda_runtime.h>
#include <cstdint>

// ============================================================================
// QuantumNeuralLayer: out = x @ W.T + (b + 0.1*q); q is batch-independent
// (the quantum transform never reads x). Main work: 262144x256x64 fp32 GEMM.
// tcgen05 is unavailable (harness targets sm_103, not sm_103a), so we use
// warp-level mma.sync m16n8k8 tf32 with W pre-rounded + fragment-reordered.
// ============================================================================

#define INV_SQRT2 0.70710678118654752440f

static constexpr int B_TOTAL = 262144;
static constexpr int KDIM    = 256;
static constexpr int ODIM    = 64;
static constexpr int TILE_M  = 128;
static constexpr int NTILES  = B_TOTAL / TILE_M;   // 2048

// SMEM (floats): A ring = 2 buffers of [128 rows][pitch 132] (conflict-free
// fragment LDS), then Wf (fragment-major W) 16384 floats.
static constexpr int APITCH  = 132;
static constexpr int ABUF_F  = TILE_M * APITCH;          // 16896 floats
static constexpr int WF_F    = 2 * ABUF_F;               // 33792 floats offset
static constexpr int SMEM_F  = WF_F + 16384;             // 50176 floats
static constexpr int SMEM_BYTES = SMEM_F * 4;            // 200704 B

__device__ float g_bias_eff[64];
__device__ float g_Wf[16384];   // [kstep 0..31][ntile 0..7][lane 0..31][2]

// ---------------------------------------------------------------------------
__device__ __forceinline__ uint32_t smem_u32(const void* p) {
    uint32_t a;
    asm("{ .reg .u64 t; cvta.to.shared.u64 t, %1; cvt.u32.u64 %0, t; }" : "=r"(a) : "l"(p));
    return a;
}
__device__ __forceinline__ void cp_async16(uint32_t s, const void* g) {
    asm volatile("cp.async.cg.shared.global [%0], [%1], 16;" :: "r"(s), "l"(g));
}
#define CP_COMMIT() asm volatile("cp.async.commit_group;" ::: "memory")
#define CP_WAIT_1() asm volatile("cp.async.wait_group 1;" ::: "memory")
#define CP_WAIT_0() asm volatile("cp.async.wait_group 0;" ::: "memory")

__device__ __forceinline__ uint32_t f2tf32(float f) {
    uint32_t u;
    asm("cvt.rna.tf32.f32 %0, %1;" : "=r"(u) : "f"(f));
    return u;
}

__device__ __forceinline__ void mma_tf32(float c[4], uint32_t a0, uint32_t a1,
                                         uint32_t a2, uint32_t a3,
                                         uint32_t b0, uint32_t b1) {
    asm volatile(
        "mma.sync.aligned.m16n8k8.row.col.f32.tf32.tf32.f32 "
        "{%0,%1,%2,%3}, {%4,%5,%6,%7}, {%8,%9}, {%0,%1,%2,%3};"
        : "+f"(c[0]), "+f"(c[1]), "+f"(c[2]), "+f"(c[3])
        : "r"(a0), "r"(a1), "r"(a2), "r"(a3), "r"(b0), "r"(b1));
}

// ---------------------------------------------------------------------------
// Prep: bias_eff = b + 0.1*quantum (batch-independent) and W in tf32-rounded
// fragment-major layout so the GEMM's B operand is one conflict-free LDS.64.
// ---------------------------------------------------------------------------
__global__ void qnl_prep_kernel(const float* __restrict__ b,
                                const float* __restrict__ phase,
                                const float* __restrict__ ent,
                                const float* __restrict__ W) {
    __shared__ float ha[64], hc[64];
    const int tid = threadIdx.x;
    float a = 1.0f, c = 0.0f;
    for (int d = 0; d < 3; d++) {
        if (tid < 64) {
            float ph = phase[d * 64 + tid];
            ha[tid] = (a + c) * INV_SQRT2 * sinf(ph);
            hc[tid] = (a - c) * INV_SQRT2 * cosf(ph);
        }
        __syncthreads();
        if (tid < 64) {
            float sa = 0.0f, sc = 0.0f;
#pragma unroll
            for (int i = 0; i < 64; i++) {
                float e = ent[i * 64 + tid];
                sa += ha[i] * e;
                sc += hc[i] * e;
            }
            a = sa; c = sc;
        }
        __syncthreads();
    }
    if (tid < 64) g_bias_eff[tid] = b[tid] + 0.1f * (a * a + c * c);

    // Wf[e] for e = (s*8 + nt)*32 + lane: b0 = W[n, k], b1 = W[n, k+4]
    for (int e = tid; e < 8192; e += 256) {
        int lane = e & 31;
        int nt   = (e >> 5) & 7;
        int s    = e >> 8;
        int n = nt * 8 + (lane >> 2);
        int k = s * 8 + (lane & 3);
        g_Wf[2 * e + 0] = __uint_as_float(f2tf32(W[n * KDIM + k]));
        g_Wf[2 * e + 1] = __uint_as_float(f2tf32(W[n * KDIM + k + 4]));
    }
}

// ---------------------------------------------------------------------------
// Main GEMM: persistent CTAs, mma.sync tf32, double-buffered K-halves.
// ---------------------------------------------------------------------------
__global__ void __launch_bounds__(256, 1)
qnl_gemm_kernel(const float* __restrict__ x, float* __restrict__ out) {
    extern __shared__ float smemf[];
    const uint32_t sb = smem_u32(smemf);
    const int tid  = threadIdx.x;
    const int wid  = tid >> 5;
    const int lane = tid & 31;
    const int grid = gridDim.x;
    const int bid  = blockIdx.x;

    // Stage Wf into SMEM (joins cp.async group 0)
#pragma unroll
    for (int i = 0; i < 16; i++) {
        int chunk = tid + 256 * i;   // 4096 x 16B
        cp_async16(sb + (uint32_t)(WF_F * 4) + chunk * 16, g_Wf + chunk * 4);
    }

    // Bias fragments in registers: per ntile, cols {2*(lane&3), +1}
    float2 bias[8];
#pragma unroll
    for (int nt = 0; nt < 8; nt++) {
        int col = nt * 8 + 2 * (lane & 3);
        bias[nt].x = g_bias_eff[col];
        bias[nt].y = g_bias_eff[col + 1];
    }

    const int ntile_local = (NTILES - bid + grid - 1) / grid;
    const int H = 2 * ntile_local;   // steps = (tile, k-half)

    // Load K-half j into buffer (j&1): [128 rows][128 k] as pitch-132 floats.
    auto load_half = [&](int j) {
        const int tile = bid + (j >> 1) * grid;
        const int h = j & 1;
        const float* src = x + (size_t)tile * TILE_M * KDIM + h * 128;
        const uint32_t abase = sb + (uint32_t)(h * ABUF_F * 4);
#pragma unroll
        for (int i = 0; i < 16; i++) {
            int c  = tid + 256 * i;   // 4096 x 16B
            int r  = c >> 5;
            int kc = c & 31;          // 16B chunk within 128-float half-row
            cp_async16(abase + (uint32_t)(r * APITCH + kc * 4) * 4,
                       src + (size_t)r * KDIM + kc * 4);
        }
        CP_COMMIT();
    };

    load_half(0);

    float acc[8][4];
#pragma unroll
    for (int nt = 0; nt < 8; nt++)
#pragma unroll
        for (int q = 0; q < 4; q++) acc[nt][q] = 0.0f;

    const int wrow = wid * 16;
    const int arow = wrow + (lane >> 2);

    for (int j = 0; j < H; j++) {
        if (j + 1 < H) {
            load_half(j + 1);
            CP_WAIT_1();
        } else {
            CP_WAIT_0();
        }
        __syncthreads();

        const int h = j & 1;
        const float* Ab = smemf + h * ABUF_F + arow * APITCH + (lane & 3);
        const float2* Wb = (const float2*)(smemf + WF_F) + h * 16 * 8 * 32;

#pragma unroll
        for (int s = 0; s < 16; s++) {
            uint32_t a0 = f2tf32(Ab[8 * s]);
            uint32_t a1 = f2tf32(Ab[8 * s + 8 * APITCH]);
            uint32_t a2 = f2tf32(Ab[8 * s + 4]);
            uint32_t a3 = f2tf32(Ab[8 * s + 8 * APITCH + 4]);
#pragma unroll
            for (int nt = 0; nt < 8; nt++) {
                float2 wf = Wb[(s * 8 + nt) * 32 + lane];
                mma_tf32(acc[nt], a0, a1, a2, a3,
                         __float_as_uint(wf.x), __float_as_uint(wf.y));
            }
        }

        if (h) {
            // Tile done: epilogue (accumulators are register-resident).
            const int tile = bid + (j >> 1) * grid;
            const int row0 = tile * TILE_M + arow;
            float* o0 = out + (size_t)row0 * ODIM + 2 * (lane & 3);
#pragma unroll
            for (int nt = 0; nt < 8; nt++) {
                float2 v0 = {acc[nt][0] + bias[nt].x, acc[nt][1] + bias[nt].y};
                float2 v1 = {acc[nt][2] + bias[nt].x, acc[nt][3] + bias[nt].y};
                *(float2*)(o0 + nt * 8)              = v0;
                *(float2*)(o0 + nt * 8 + 8 * ODIM)   = v1;
                acc[nt][0] = acc[nt][1] = acc[nt][2] = acc[nt][3] = 0.0f;
            }
        }
        __syncthreads();
    }
}

// ---------------------------------------------------------------------------
extern "C" void kernel_launch(void* const* d_in, const int* in_sizes, int n_in,
                              void* d_out, int out_size) {
    const float* x   = (const float*)d_in[0];
    const float* W   = (const float*)d_in[1];
    const float* b   = (const float*)d_in[2];
    const float* ps  = (const float*)d_in[3];
    const float* ent = (const float*)d_in[4];
    float* out = (float*)d_out;

    qnl_prep_kernel<<<1, 256>>>(b, ps, ent, W);

    cudaFuncSetAttribute(qnl_gemm_kernel,
                         cudaFuncAttributeMaxDynamicSharedMemorySize, SMEM_BYTES);

    int sm = 148;
    cudaDeviceGetAttribute(&sm, cudaDevAttrMultiProcessorCount, 0);
    int grid = sm < NTILES ? sm : NTILES;

    qnl_gemm_kernel<<<grid, 256, SMEM_BYTES>>>(x, out);
}